// round 10
// baseline (speedup 1.0000x reference)
#include <cuda_runtime.h>
#include <cuda_bf16.h>

// word_vecs [B=2048, S=200, D=300] fp32 -> masked mean over S -> [B, D].
// All-zero words contribute 0 to the sum, so only the COUNT needs the mask.
//
// Full-lane 128-thread variant: grid=2048 (fully resident, single wave) but
// zero idle lanes. Each iteration covers a WORD PAIR (150 contiguous float4):
// thread t loads float4 150q+t; threads 0..21 also load 150q+128+t. Every
// thread's dim-group is fixed, so sums stay in registers; a 2.4KB shared
// staging combines even/odd partials at the end. Resident warps 6144 -> 8192
// (+33%) at identical in-flight bytes (unroll 2 x 150 == unroll 4 x 75).
// (Resubmission of R9 — previous run died to a container/infra failure.)

#define B_DIM 2048
#define S_DIM 200
#define PAIRS 100
#define WPAIR 150        // float4 per word pair
#define NTHREADS 128
#define SENT_F4 (S_DIM * 75)

__device__ __forceinline__ bool f4_nz(float4 v) {
    return (v.x != 0.f) || (v.y != 0.f) || (v.z != 0.f) || (v.w != 0.f);
}

__global__ __launch_bounds__(NTHREADS)
void sentence_rep_kernel(const float4* __restrict__ in, float4* __restrict__ out) {
    __shared__ unsigned char flags[S_DIM];
    __shared__ float4 sEven[75];
    __shared__ float4 sOdd[75];
    __shared__ float inv_count;

    const int b = blockIdx.x;
    const int t = threadIdx.x;

    for (int i = t; i < S_DIM; i += NTHREADS) flags[i] = 0;
    __syncthreads();

    const float4* __restrict__ base = in + (size_t)b * SENT_F4;

    float4 a0 = make_float4(0.f, 0.f, 0.f, 0.f);   // all threads
    float4 a1 = make_float4(0.f, 0.f, 0.f, 0.f);   // threads 0..21 only

    #pragma unroll 2
    for (int q = 0; q < PAIRS; ++q) {
        const float4* pq = base + q * WPAIR;

        float4 v0 = __ldcs(pq + t);                // flat 150q + t
        a0.x += v0.x; a0.y += v0.y; a0.z += v0.z; a0.w += v0.w;
        // word index: t<75 -> even word 2q, t>=75 -> odd word 2q+1
        if (f4_nz(v0)) flags[2 * q + (t >= 75)] = 1;   // benign same-value race

        if (t < 22) {
            float4 v1 = __ldcs(pq + 128 + t);      // odd word, dims 53+t
            a1.x += v1.x; a1.y += v1.y; a1.z += v1.z; a1.w += v1.w;
            if (f4_nz(v1)) flags[2 * q + 1] = 1;
        }
    }

    // stage partials: even-word dims from t<75, odd-word dims from t>=75 & a1
    if (t < 75) sEven[t] = a0;
    else        sOdd[t - 75] = a0;                 // odd dims 0..52
    if (t < 22) sOdd[53 + t] = a1;                 // odd dims 53..74
    __syncthreads();

    if (t < 32) {
        int c = 0;
        for (int i = t; i < S_DIM; i += 32) c += (int)flags[i];
        #pragma unroll
        for (int o = 16; o > 0; o >>= 1) c += __shfl_down_sync(0xffffffffu, c, o);
        if (t == 0) inv_count = 1.0f / (float)c;   // count >= 1 guaranteed
    }
    __syncthreads();

    if (t < 75) {
        const float ic = inv_count;
        float4 e = sEven[t], o = sOdd[t];
        out[(size_t)b * 75 + t] = make_float4((e.x + o.x) * ic,
                                              (e.y + o.y) * ic,
                                              (e.z + o.z) * ic,
                                              (e.w + o.w) * ic);
    }
}

extern "C" void kernel_launch(void* const* d_in, const int* in_sizes, int n_in,
                              void* d_out, int out_size) {
    (void)in_sizes; (void)n_in; (void)out_size;
    const float4* in = (const float4*)d_in[0];
    float4* out = (float4*)d_out;
    sentence_rep_kernel<<<B_DIM, NTHREADS>>>(in, out);
}

// round 11
// speedup vs baseline: 1.5789x; 1.5789x over previous
#include <cuda_runtime.h>
#include <cuda_bf16.h>

// Problem: word_vecs [B=2048, S=200, D=300] fp32 -> masked mean over S -> [B, D].
// A masked (all-zero) word contributes 0 to the sum, so the sum needs no mask;
// only the count does.
//
// FINAL: byte-identical resubmission of the R5 winner (77.66us, 6355 GB/s ==
// ~99.6% of the full-chip LTS streaming cap). Six structural variants (chunked
// count reduction, sentence split, unroll 8, float8 loads, grid 1024, full-lane
// 128-thread remap) all regressed 8-58%; the per-word-paced float4 stream with
// 4 independent LDG.128 in flight per thread is the empirically optimal
// operating point for this access pattern on sm_100a.

#define B_DIM 2048
#define S_DIM 200
#define D_DIM 300
#define VDIM  75   // 300 floats = 75 float4 per word (1200 B, 16B-aligned stride)
#define NTHREADS 96

__global__ __launch_bounds__(NTHREADS)
void sentence_rep_kernel(const float4* __restrict__ in, float4* __restrict__ out) {
    __shared__ unsigned char flags[S_DIM];
    __shared__ float inv_count;

    const int b = blockIdx.x;
    const int t = threadIdx.x;
    const bool active = (t < VDIM);

    // zero the per-word flags
    for (int i = t; i < S_DIM; i += NTHREADS) flags[i] = 0;
    __syncthreads();

    const float4* __restrict__ row = in + (size_t)b * (S_DIM * VDIM);

    float4 acc = make_float4(0.f, 0.f, 0.f, 0.f);

    #pragma unroll 4
    for (int s = 0; s < S_DIM; ++s) {
        float4 v = make_float4(0.f, 0.f, 0.f, 0.f);
        if (active) v = __ldcs(&row[s * VDIM + t]);
        acc.x += v.x; acc.y += v.y; acc.z += v.z; acc.w += v.w;

        // per-word any-nonzero predicate (benign-race write of the same value)
        bool nz = (v.x != 0.f) || (v.y != 0.f) || (v.z != 0.f) || (v.w != 0.f);
        unsigned m = __ballot_sync(0xffffffffu, nz);
        if (((t & 31) == 0) && m) flags[s] = 1;
    }
    __syncthreads();

    // warp 0 reduces the 200 flags -> count -> 1/count
    if (t < 32) {
        int c = 0;
        for (int i = t; i < S_DIM; i += 32) c += (int)flags[i];
        #pragma unroll
        for (int o = 16; o > 0; o >>= 1) c += __shfl_down_sync(0xffffffffu, c, o);
        if (t == 0) inv_count = 1.0f / (float)c;   // count >= 1 guaranteed
    }
    __syncthreads();

    if (active) {
        const float ic = inv_count;
        out[(size_t)b * VDIM + t] =
            make_float4(acc.x * ic, acc.y * ic, acc.z * ic, acc.w * ic);
    }
}

extern "C" void kernel_launch(void* const* d_in, const int* in_sizes, int n_in,
                              void* d_out, int out_size) {
    (void)in_sizes; (void)n_in; (void)out_size;
    const float4* in = (const float4*)d_in[0];
    float4* out = (float4*)d_out;
    sentence_rep_kernel<<<B_DIM, NTHREADS>>>(in, out);
}